// round 5
// baseline (speedup 1.0000x reference)
#include <cuda_runtime.h>
#include <cstdint>

#define BSZ   2
#define C_IN  64
#define NPTS  1024
#define NA    60
#define NO    60
#define KS    3
#define ANN   8
#define CO    128
#define CK    192            // GEMM K
#define NCOLS (NPTS * NO)    // 61440  (GEMM N per b)
#define NT    128            // GEMM N tile
#define NTILES_B (NCOLS / NT)       // 480
#define TILES    (BSZ * NTILES_B)   // 960
#define GRID_GEMM 148

#define WPAD 196             // W smem row stride (floats): conflict-free frag loads
#define BQROW 16             // float4 quads per B row (16 * 16B = 256B, no pad; XOR swizzle)
#define BQBUF (NT * BQROW)   // float4s per B chunk buffer (2048)

// ---------------- device scratch ----------------
// x^T layout: [b][n][k], k contiguous (768B rows)
__device__ float g_x[(size_t)BSZ * NCOLS * CK];   // 94.4 MB

// ---------------- helpers ----------------
__device__ __forceinline__ float tf32r(float x) {
    float r; asm("cvt.rna.tf32.f32 %0, %1;" : "=f"(r) : "f"(x)); return r;
}
__device__ __forceinline__ void mma_tf32(float* d, const uint32_t* a, uint32_t b0, uint32_t b1) {
    asm volatile("mma.sync.aligned.m16n8k8.row.col.f32.tf32.tf32.f32 "
        "{%0,%1,%2,%3}, {%4,%5,%6,%7}, {%8,%9}, {%0,%1,%2,%3};"
        : "+f"(d[0]), "+f"(d[1]), "+f"(d[2]), "+f"(d[3])
        : "r"(a[0]), "r"(a[1]), "r"(a[2]), "r"(a[3]), "r"(b0), "r"(b1));
}

// ---------------- kernel 1: gather + intra-weight combine ----------------
// One CTA per (p-pair, b). Two points share all (w, idx) smem reads.
// Output: g_x[b][n][k], n = p*60+o, k = c*3+kk.
__global__ __launch_bounds__(256) void k_gather(const float* __restrict__ feats,
                                                const float* __restrict__ wv,
                                                const int*   __restrict__ widx) {
    extern __shared__ float smem1[];
    float*  Xs = smem1;                        // 2 * 64 * 61 = 7808
    float*  Gr = Xs + 2 * C_IN * (NA + 1);     // 2 * 60 * 192 = 23040  [pp][o][ck]
    float2* pk = (float2*)(Gr + 2 * NO * CK);  // 1440 float2 (w, idx-bits)

    const int XS1 = C_IN * (NA + 1);           // 3904
    const int GR1 = NO * CK;                   // 11520

    int tid = threadIdx.x;
    int pb = blockIdx.x, b = blockIdx.y;       // points 2*pb, 2*pb+1

    for (int i = tid; i < NO * KS * ANN; i += 256)
        pk[i] = make_float2(wv[i], __int_as_float(widx[i]));

    // feats rows for both points are contiguous (120 floats per c)
    const float* fb = feats + ((size_t)b * C_IN * NPTS + 2 * pb) * NA;
    for (int i = tid; i < C_IN * 2 * NA; i += 256) {
        int c = i / (2 * NA), q = i - c * (2 * NA);
        int pp = q / NA, a = q - pp * NA;
        Xs[pp * XS1 + c * (NA + 1) + a] = fb[(size_t)c * NPTS * NA + q];
    }
    __syncthreads();

    int c = tid & 63, g = tid >> 6;
    const float* x0 = Xs + c * (NA + 1);
    const float* x1 = x0 + XS1;
    for (int ok = g; ok < NO * KS; ok += 4) {
        int o = ok / KS, k = ok - o * KS;
        const float2* pp8 = pk + ok * ANN;
        float a0 = 0.f, a1 = 0.f;
        #pragma unroll
        for (int j = 0; j < ANN; ++j) {
            float2 wi = pp8[j];
            int ix = __float_as_int(wi.y);
            a0 += wi.x * x0[ix];
            a1 += wi.x * x1[ix];
        }
        Gr[o * CK + c * KS + k]       = a0;
        Gr[GR1 + o * CK + c * KS + k] = a1;
    }
    __syncthreads();

    // contiguous write: 120 rows of 192 floats
    float* xb = g_x + ((size_t)b * NCOLS + (size_t)pb * 2 * NO) * CK;
    const float4* Gr4 = (const float4*)Gr;
    float4* xb4 = (float4*)xb;
    for (int i = tid; i < 2 * NO * CK / 4; i += 256) xb4[i] = Gr4[i];
}

// ---------------- kernel 2: mma.sync TF32 GEMM (3xTF32 split) ----------------
// 512 threads, 16 warps (4m x 4n of 32x32 warp tiles). B pre-split into hi/lo
// quads {h(k), l(k), h(k+4), l(k+4)} with XOR-4 swizzle -> 1 LDS.128 per frag.
__global__ __launch_bounds__(512, 1) void k_gemm_mma(const float* __restrict__ W,
                                                     const float* __restrict__ bias,
                                                     float* __restrict__ out) {
    extern __shared__ float sm[];
    float*  Wsm = sm;                              // 128 * 196
    float4* Bq  = (float4*)(sm + CO * WPAD);       // 2 * 2048 float4

    int tid = threadIdx.x;
    int wid = tid >> 5, lane = tid & 31;
    int wm = (wid & 3) * 32;             // warp m-offset
    int wn = (wid >> 2) * 32;            // warp n-offset
    int lr = lane >> 2, lc = lane & 3;

    // B-chunk loader mapping: thread <-> (n, ks)
    int bn = tid >> 2, bks = tid & 3;

    for (int i = tid * 4; i < CO * CK; i += 2048) {
        int m = i / CK, k = i - m * CK;
        *(float4*)(Wsm + m * WPAD + k) = *(const float4*)(W + i);
    }
    float bz[2][2];
    #pragma unroll
    for (int mt = 0; mt < 2; ++mt) {
        bz[mt][0] = bias[wm + mt * 16 + lr];
        bz[mt][1] = bias[wm + mt * 16 + lr + 8];
    }
    __syncthreads();

    for (int t = blockIdx.x; t < TILES; t += GRID_GEMM) {
        int b = t / NTILES_B;
        int n0 = (t - b * NTILES_B) * NT;
        const float* xrow = g_x + ((size_t)b * NCOLS + n0 + bn) * CK + bks * 8;

        // prefetch chunk 0: 8 consecutive k for row bn
        float4 p0 = *(const float4*)(xrow);
        float4 p1 = *(const float4*)(xrow + 4);

        float d[2][4][4];
        #pragma unroll
        for (int mt = 0; mt < 2; ++mt)
            #pragma unroll
            for (int nt = 0; nt < 4; ++nt)
                #pragma unroll
                for (int r = 0; r < 4; ++r) d[mt][nt][r] = 0.f;

        #pragma unroll 1
        for (int ch = 0; ch < 6; ++ch) {
            float4* buf = Bq + (ch & 1) * BQBUF;
            // store quads: e = 0..3, quad {h(k), l(k), h(k+4), l(k+4)}
            {
                float h0[4], l0[4], h1[4], l1[4];
                h0[0]=tf32r(p0.x); l0[0]=tf32r(p0.x-h0[0]);
                h0[1]=tf32r(p0.y); l0[1]=tf32r(p0.y-h0[1]);
                h0[2]=tf32r(p0.z); l0[2]=tf32r(p0.z-h0[2]);
                h0[3]=tf32r(p0.w); l0[3]=tf32r(p0.w-h0[3]);
                h1[0]=tf32r(p1.x); l1[0]=tf32r(p1.x-h1[0]);
                h1[1]=tf32r(p1.y); l1[1]=tf32r(p1.y-h1[1]);
                h1[2]=tf32r(p1.z); l1[2]=tf32r(p1.z-h1[2]);
                h1[3]=tf32r(p1.w); l1[3]=tf32r(p1.w-h1[3]);
                int sw = (bn & 1) << 2;
                #pragma unroll
                for (int e = 0; e < 4; ++e) {
                    int x = (bks * 4 + e) ^ sw;
                    buf[bn * BQROW + x] = make_float4(h0[e], l0[e], h1[e], l1[e]);
                }
            }
            __syncthreads();
            if (ch < 5) {
                p0 = *(const float4*)(xrow + (ch + 1) * 32);
                p1 = *(const float4*)(xrow + (ch + 1) * 32 + 4);
            }
            // mma over 4 k-steps of 8
            #pragma unroll
            for (int ks = 0; ks < 4; ++ks) {
                uint32_t ah[2][4], al[2][4];
                #pragma unroll
                for (int mt = 0; mt < 2; ++mt)
                    #pragma unroll
                    for (int r = 0; r < 4; ++r) {
                        int row = wm + mt * 16 + lr + (r & 1) * 8;
                        int col = ch * 32 + ks * 8 + lc + (r >> 1) * 4;
                        float v = Wsm[row * WPAD + col];
                        float h = tf32r(v);
                        ah[mt][r] = __float_as_uint(h);
                        al[mt][r] = __float_as_uint(tf32r(v - h));
                    }
                #pragma unroll
                for (int nt = 0; nt < 4; ++nt) {
                    int row = wn + nt * 8 + lr;
                    int x = (ks * 4 + lc) ^ ((row & 1) << 2);
                    float4 q = buf[row * BQROW + x];
                    uint32_t bh0 = __float_as_uint(q.x), bl0 = __float_as_uint(q.y);
                    uint32_t bh1 = __float_as_uint(q.z), bl1 = __float_as_uint(q.w);
                    #pragma unroll
                    for (int mt = 0; mt < 2; ++mt) {
                        mma_tf32(d[mt][nt], ah[mt], bh0, bh1);
                        mma_tf32(d[mt][nt], ah[mt], bl0, bl1);
                        mma_tf32(d[mt][nt], al[mt], bh0, bh1);
                    }
                }
            }
        }

        // epilogue: direct STG.64 (+bias)
        #pragma unroll
        for (int mt = 0; mt < 2; ++mt) {
            int m0 = wm + mt * 16 + lr;
            size_t ro0 = ((size_t)b * CO + m0) * NCOLS + n0 + wn + 2 * lc;
            size_t ro1 = ro0 + (size_t)8 * NCOLS;
            #pragma unroll
            for (int nt = 0; nt < 4; ++nt) {
                float2 v0 = { d[mt][nt][0] + bz[mt][0], d[mt][nt][1] + bz[mt][0] };
                float2 v1 = { d[mt][nt][2] + bz[mt][1], d[mt][nt][3] + bz[mt][1] };
                *(float2*)(out + ro0 + nt * 8) = v0;
                *(float2*)(out + ro1 + nt * 8) = v1;
            }
        }
        __syncthreads();   // protect Bq buf0 before next tile's first store
    }
}

// ---------------- host launcher ----------------
extern "C" void kernel_launch(void* const* d_in, const int* in_sizes, int n_in,
                              void* d_out, int out_size) {
    const float* feats     = (const float*)d_in[0];  // (2,64,1024,60) f32
    const float* intra_w   = (const float*)d_in[1];  // (60,3,8) f32
    const float* W         = (const float*)d_in[2];  // (128,192) f32
    const float* bias      = (const float*)d_in[3];  // (1,128,1) f32
    const int*   intra_idx = (const int*)d_in[4];    // (60,3,8) i32
    float* out = (float*)d_out;

    const int SMEM1 = (2 * C_IN * (NA + 1) + 2 * NO * CK + 2 * NO * KS * ANN) * 4; // 134912
    const int SMEM2 = (CO * WPAD) * 4 + 2 * BQBUF * 16;                            // 165888

    static int configured = 0;
    if (!configured) {
        cudaFuncSetAttribute(k_gather,   cudaFuncAttributeMaxDynamicSharedMemorySize, SMEM1);
        cudaFuncSetAttribute(k_gemm_mma, cudaFuncAttributeMaxDynamicSharedMemorySize, SMEM2);
        configured = 1;
    }

    k_gather<<<dim3(NPTS / 2, BSZ), 256, SMEM1>>>(feats, intra_w, intra_idx);
    k_gemm_mma<<<GRID_GEMM, 512, SMEM2>>>(W, bias, out);
}

// round 6
// speedup vs baseline: 1.5243x; 1.5243x over previous
#include <cuda_runtime.h>
#include <cuda_bf16.h>
#include <cstdint>

#define BSZ   2
#define C_IN  64
#define NPTS  1024
#define NA    60
#define NO    60
#define KS    3
#define ANN   8
#define CO    128
#define CK    192            // GEMM K
#define NCOLS (NPTS * NO)    // 61440  (GEMM N per b)
#define NT    128            // GEMM N tile
#define NTILES_B (NCOLS / NT)       // 480
#define TILES    (BSZ * NTILES_B)   // 960
#define GRID_GEMM 148

#define AQROW 52             // uint4 quads per W row (48 used, pad: phase-conflict-free)
#define BQROW 11             // uint4 quads per B row (8 used, pad: phase-conflict-free)
#define BQBUF (NT * BQROW)   // quads per B chunk buffer

// ---------------- device scratch ----------------
// x^T layout: [b][n][k], k contiguous (768B rows)
__device__ float g_x[(size_t)BSZ * NCOLS * CK];   // 94.4 MB

// ---------------- helpers ----------------
__device__ __forceinline__ void mma_bf16(float* d, const uint32_t* a, uint32_t b0, uint32_t b1) {
    asm volatile("mma.sync.aligned.m16n8k16.row.col.f32.bf16.bf16.f32 "
        "{%0,%1,%2,%3}, {%4,%5,%6,%7}, {%8,%9}, {%0,%1,%2,%3};"
        : "+f"(d[0]), "+f"(d[1]), "+f"(d[2]), "+f"(d[3])
        : "r"(a[0]), "r"(a[1]), "r"(a[2]), "r"(a[3]), "r"(b0), "r"(b1));
}
// pack (v0,v1) -> bf16x2 hi, and residuals -> bf16x2 lo
__device__ __forceinline__ void split2(float v0, float v1, uint32_t& h, uint32_t& l) {
    __nv_bfloat162 hh = __floats2bfloat162_rn(v0, v1);
    float h0 = __bfloat162float(hh.x), h1 = __bfloat162float(hh.y);
    __nv_bfloat162 ll = __floats2bfloat162_rn(v0 - h0, v1 - h1);
    h = *(uint32_t*)&hh;
    l = *(uint32_t*)&ll;
}

// ---------------- kernel 1: gather + intra-weight combine ----------------
// One CTA per (p, b); half-size staging (two flushes) -> 49KB smem -> 4 CTA/SM.
__global__ __launch_bounds__(256, 4) void k_gather(const float* __restrict__ feats,
                                                   const float* __restrict__ wv,
                                                   const int*   __restrict__ widx) {
    extern __shared__ float smem1[];
    float*  Xs = smem1;                        // 64 * 61 = 3904
    float*  Gr = Xs + C_IN * (NA + 1);         // 30 * 192 = 5760 (half of o-range)
    float2* pk = (float2*)(Gr + 30 * CK);      // 1440 float2

    int tid = threadIdx.x;
    int p = blockIdx.x, b = blockIdx.y;

    for (int i = tid; i < NO * KS * ANN; i += 256)
        pk[i] = make_float2(wv[i], __int_as_float(widx[i]));

    const float* fb = feats + ((size_t)b * C_IN * NPTS + p) * NA;
    for (int i = tid; i < C_IN * NA; i += 256) {
        int c = i / NA, a = i - c * NA;
        Xs[c * (NA + 1) + a] = fb[(size_t)c * NPTS * NA + a];
    }
    __syncthreads();

    int c = tid & 63, g = tid >> 6;
    const float* x0 = Xs + c * (NA + 1);

    #pragma unroll 1
    for (int half = 0; half < 2; ++half) {
        int ok0 = half * 90;
        for (int ok = ok0 + g; ok < ok0 + 90; ok += 4) {
            int o = ok / KS, k = ok - o * KS;
            const float2* pp8 = pk + ok * ANN;
            float acc = 0.f;
            #pragma unroll
            for (int j = 0; j < ANN; ++j) {
                float2 wi = pp8[j];
                acc += wi.x * x0[__float_as_int(wi.y)];
            }
            Gr[(o - half * 30) * CK + c * KS + k] = acc;
        }
        __syncthreads();
        // flush 30 rows of 192 floats, fully coalesced
        float* xb = g_x + ((size_t)b * NCOLS + (size_t)p * NO + half * 30) * CK;
        const float4* Gr4 = (const float4*)Gr;
        float4* xb4 = (float4*)xb;
        for (int i = tid; i < 30 * CK / 4; i += 256) xb4[i] = Gr4[i];
        __syncthreads();
    }
}

// ---------------- kernel 2: bf16 3-term mma GEMM ----------------
// 512 threads, 16 warps: 2 M-warpgroups (rows 0-63 / 64-127), each 4m x 2n,
// warp tile 16m x 64n. W pre-split hi/lo quads in smem; B chunks (32k x 128n)
// converted to hi/lo pair-quads, double-buffered.
__global__ __launch_bounds__(512, 1) void k_gemm_mma(const float* __restrict__ W,
                                                     const float* __restrict__ bias,
                                                     float* __restrict__ out) {
    extern __shared__ uint4 smq[];
    uint4* Aq = smq;                 // 128 * AQROW
    uint4* Bq = smq + CO * AQROW;    // 2 * BQBUF

    int tid = threadIdx.x;
    int wid = tid >> 5, lane = tid & 31;
    int lr = lane >> 2, lc = lane & 3;
    int wg = wid >> 3;                       // m-half
    int wm = wg * 64 + (wid & 3) * 16;       // warp m-offset (16-row tile)
    int wn = ((wid >> 2) & 1) * 64;          // warp n-offset (64-col tile)

    // ---- build W hi/lo quads (one-time) ----
    {
        int r = tid >> 2, sub = tid & 3;     // 4 threads per row, 3 ks each
        const float* wr = W + (size_t)r * CK;
        #pragma unroll
        for (int s = 0; s < 3; ++s) {
            int ks = sub * 3 + s;
            #pragma unroll
            for (int c4 = 0; c4 < 4; ++c4) {
                int k0 = ks * 16 + 2 * c4;
                uint32_t h01, l01, h89, l89;
                split2(wr[k0],     wr[k0 + 1], h01, l01);
                split2(wr[k0 + 8], wr[k0 + 9], h89, l89);
                Aq[r * AQROW + ks * 4 + c4] = make_uint4(h01, l01, h89, l89);
            }
        }
    }
    float bz0 = bias[wm + lr], bz1 = bias[wm + lr + 8];
    __syncthreads();

    // B-chunk loader mapping: thread <-> (n = tid>>2, q = tid&3); k = q*8..q*8+7
    int bn = tid >> 2, bq = tid & 3;
    int bksl = bq >> 1, bpart = bq & 1;

    for (int t = blockIdx.x; t < TILES; t += GRID_GEMM) {
        int b = t / NTILES_B;
        int n0 = (t - b * NTILES_B) * NT;
        const float* xrow = g_x + ((size_t)b * NCOLS + n0 + bn) * CK + bq * 8;

        float4 p0 = *(const float4*)(xrow);
        float4 p1 = *(const float4*)(xrow + 4);

        float d[8][4];
        #pragma unroll
        for (int nt = 0; nt < 8; ++nt)
            #pragma unroll
            for (int r = 0; r < 4; ++r) d[nt][r] = 0.f;

        #pragma unroll 1
        for (int ch = 0; ch < 6; ++ch) {
            uint4* bb = Bq + (ch & 1) * BQBUF;
            // convert + store: 4 pairs -> 4 half-quad STS.64
            {
                uint32_t h[4], l[4];
                split2(p0.x, p0.y, h[0], l[0]);
                split2(p0.z, p0.w, h[1], l[1]);
                split2(p1.x, p1.y, h[2], l[2]);
                split2(p1.z, p1.w, h[3], l[3]);
                uint2* bb2 = (uint2*)bb;
                #pragma unroll
                for (int m = 0; m < 4; ++m)
                    bb2[(bn * BQROW + bksl * 4 + m) * 2 + bpart] = make_uint2(h[m], l[m]);
            }
            __syncthreads();
            if (ch < 5) {
                p0 = *(const float4*)(xrow + (ch + 1) * 32);
                p1 = *(const float4*)(xrow + (ch + 1) * 32 + 4);
            }
            // mma: 2 k16-steps per chunk
            #pragma unroll
            for (int ksl = 0; ksl < 2; ++ksl) {
                int ks = ch * 2 + ksl;
                uint4 q1 = Aq[(wm + lr) * AQROW + ks * 4 + lc];
                uint4 q2 = Aq[(wm + lr + 8) * AQROW + ks * 4 + lc];
                uint32_t ah[4] = {q1.x, q2.x, q1.z, q2.z};
                uint32_t al[4] = {q1.y, q2.y, q1.w, q2.w};
                #pragma unroll
                for (int nt = 0; nt < 8; ++nt) {
                    int nrow = wn + nt * 8 + lr;
                    uint4 qb = bb[nrow * BQROW + ksl * 4 + lc];
                    mma_bf16(d[nt], ah, qb.x, qb.z);
                    mma_bf16(d[nt], ah, qb.y, qb.w);
                    mma_bf16(d[nt], al, qb.x, qb.z);
                }
            }
        }

        // epilogue: direct STG.64 (+bias); no extra sync needed (double buffer)
        size_t ro0 = ((size_t)b * CO + wm + lr) * NCOLS + n0 + wn + 2 * lc;
        size_t ro1 = ro0 + (size_t)8 * NCOLS;
        #pragma unroll
        for (int nt = 0; nt < 8; ++nt) {
            float2 v0 = { d[nt][0] + bz0, d[nt][1] + bz0 };
            float2 v1 = { d[nt][2] + bz1, d[nt][3] + bz1 };
            *(float2*)(out + ro0 + nt * 8) = v0;
            *(float2*)(out + ro1 + nt * 8) = v1;
        }
    }
}

// ---------------- host launcher ----------------
extern "C" void kernel_launch(void* const* d_in, const int* in_sizes, int n_in,
                              void* d_out, int out_size) {
    const float* feats     = (const float*)d_in[0];  // (2,64,1024,60) f32
    const float* intra_w   = (const float*)d_in[1];  // (60,3,8) f32
    const float* W         = (const float*)d_in[2];  // (128,192) f32
    const float* bias      = (const float*)d_in[3];  // (1,128,1) f32
    const int*   intra_idx = (const int*)d_in[4];    // (60,3,8) i32
    float* out = (float*)d_out;

    const int SMEM1 = (C_IN * (NA + 1) + 30 * CK) * 4 + NO * KS * ANN * 8;   // 50176
    const int SMEM2 = (CO * AQROW + 2 * BQBUF) * 16;                          // 151552

    static int configured = 0;
    if (!configured) {
        cudaFuncSetAttribute(k_gather,   cudaFuncAttributeMaxDynamicSharedMemorySize, SMEM1);
        cudaFuncSetAttribute(k_gemm_mma, cudaFuncAttributeMaxDynamicSharedMemorySize, SMEM2);
        configured = 1;
    }

    k_gather<<<dim3(NPTS, BSZ), 256, SMEM1>>>(feats, intra_w, intra_idx);
    k_gemm_mma<<<GRID_GEMM, 512, SMEM2>>>(W, bias, out);
}

// round 10
// speedup vs baseline: 1.5873x; 1.0413x over previous
#include <cuda_runtime.h>
#include <cuda_bf16.h>
#include <cstdint>

#define BSZ   2
#define C_IN  64
#define NPTS  1024
#define NA    60
#define NO    60
#define KS    3
#define ANN   8
#define CO    128
#define CK    192            // GEMM K
#define NCOLS (NPTS * NO)    // 61440  (GEMM N per b)
#define NT    128            // GEMM N tile
#define NTILES_B (NCOLS / NT)       // 480
#define TILES    (BSZ * NTILES_B)   // 960
#define GRID_GEMM 148

#define AQROW 52             // uint4 quads per W row (48 used; (4lr+lc)%8 distinct -> conflict-free)
#define BQROW 12             // uint4 quads per B row (8 used; loads conflict-free)
#define BQBUF (NT * BQROW)   // quads per B chunk buffer

// ---------------- device scratch ----------------
// x^T layout: [b][n][k], k contiguous (768B rows)
__device__ float g_x[(size_t)BSZ * NCOLS * CK];   // 94.4 MB

// ---------------- helpers ----------------
__device__ __forceinline__ void mma_bf16(float* d, const uint32_t* a, uint32_t b0, uint32_t b1) {
    asm volatile("mma.sync.aligned.m16n8k16.row.col.f32.bf16.bf16.f32 "
        "{%0,%1,%2,%3}, {%4,%5,%6,%7}, {%8,%9}, {%0,%1,%2,%3};"
        : "+f"(d[0]), "+f"(d[1]), "+f"(d[2]), "+f"(d[3])
        : "r"(a[0]), "r"(a[1]), "r"(a[2]), "r"(a[3]), "r"(b0), "r"(b1));
}
// pack (v0,v1) -> bf16x2 hi, residuals -> bf16x2 lo
__device__ __forceinline__ void split2(float v0, float v1, uint32_t& h, uint32_t& l) {
    __nv_bfloat162 hh = __floats2bfloat162_rn(v0, v1);
    float h0 = __bfloat162float(hh.x), h1 = __bfloat162float(hh.y);
    __nv_bfloat162 ll = __floats2bfloat162_rn(v0 - h0, v1 - h1);
    h = *(uint32_t*)&hh;
    l = *(uint32_t*)&ll;
}

// ---------------- kernel 1: gather + intra-weight combine ----------------
// One CTA per (p, b); half-size staging -> ~49KB smem -> 4 CTA/SM.
// pk broadcasts fetched as float4 (2 neighbors per LDS.128).
__global__ __launch_bounds__(256, 4) void k_gather(const float* __restrict__ feats,
                                                   const float* __restrict__ wv,
                                                   const int*   __restrict__ widx) {
    extern __shared__ float smem1[];
    float*  Xs = smem1;                        // 64 * 61 = 3904
    float*  Gr = Xs + C_IN * (NA + 1);         // 30 * 192 = 5760 (half of o-range)
    float4* pk4 = (float4*)(Gr + 30 * CK);     // 720 float4 = {w0, i0, w1, i1}

    int tid = threadIdx.x;
    int p = blockIdx.x, b = blockIdx.y;

    for (int i = tid; i < NO * KS * ANN / 2; i += 256)
        pk4[i] = make_float4(wv[2 * i], __int_as_float(widx[2 * i]),
                             wv[2 * i + 1], __int_as_float(widx[2 * i + 1]));

    const float* fb = feats + ((size_t)b * C_IN * NPTS + p) * NA;
    for (int i = tid; i < C_IN * NA; i += 256) {
        int c = i / NA, a = i - c * NA;
        Xs[c * (NA + 1) + a] = fb[(size_t)c * NPTS * NA + a];
    }
    __syncthreads();

    int c = tid & 63, g = tid >> 6;
    const float* x0 = Xs + c * (NA + 1);

    #pragma unroll 1
    for (int half = 0; half < 2; ++half) {
        int ok0 = half * 90;
        for (int ok = ok0 + g; ok < ok0 + 90; ok += 4) {
            int o = ok / KS, k = ok - o * KS;
            const float4* pp4 = pk4 + ok * 4;
            float acc = 0.f;
            #pragma unroll
            for (int j = 0; j < 4; ++j) {
                float4 wi = pp4[j];
                acc += wi.x * x0[__float_as_int(wi.y)];
                acc += wi.z * x0[__float_as_int(wi.w)];
            }
            Gr[(o - half * 30) * CK + c * KS + k] = acc;
        }
        __syncthreads();
        float* xb = g_x + ((size_t)b * NCOLS + (size_t)p * NO + half * 30) * CK;
        const float4* Gr4 = (const float4*)Gr;
        float4* xb4 = (float4*)xb;
        for (int i = tid; i < 30 * CK / 4; i += 256) xb4[i] = Gr4[i];
        __syncthreads();
    }
}

// ---------------- kernel 2: bf16 3-term mma GEMM ----------------
// 512 threads, 16 warps: warp tile 16m x 64n. W pre-split hi/lo quads in smem.
// B producer builds FULL quads (conflict-free STS.128, parity-staggered) into
// BQROW=12 rows (conflict-free LDS.128 on the consumer side).
__global__ __launch_bounds__(512, 1) void k_gemm_mma(const float* __restrict__ W,
                                                     const float* __restrict__ bias,
                                                     float* __restrict__ out) {
    extern __shared__ uint4 smq[];
    uint4* Aq = smq;                 // 128 * AQROW
    uint4* Bq = smq + CO * AQROW;    // 2 * BQBUF

    int tid = threadIdx.x;
    int wid = tid >> 5, lane = tid & 31;
    int lr = lane >> 2, lc = lane & 3;
    int wm = (wid >> 3) * 64 + (wid & 3) * 16;   // warp m-offset (16-row tile)
    int wn = ((wid >> 2) & 1) * 64;              // warp n-offset (64-col tile)

    // ---- build W hi/lo quads (one-time) ----
    {
        int r = tid >> 2, sub = tid & 3;
        const float* wr = W + (size_t)r * CK;
        #pragma unroll
        for (int s = 0; s < 3; ++s) {
            int ks = sub * 3 + s;
            #pragma unroll
            for (int c4 = 0; c4 < 4; ++c4) {
                int k0 = ks * 16 + 2 * c4;
                uint32_t h01, l01, h89, l89;
                split2(wr[k0],     wr[k0 + 1], h01, l01);
                split2(wr[k0 + 8], wr[k0 + 9], h89, l89);
                Aq[r * AQROW + ks * 4 + c4] = make_uint4(h01, l01, h89, l89);
            }
        }
    }
    float bz0 = bias[wm + lr], bz1 = bias[wm + lr + 8];
    __syncthreads();

    // B producer mapping: bn = tid>>2; (ksl, j) = tid&3.
    // Thread builds quads c4 = {2j, 2j+1} of k16-step ksl from float4s at
    // k = ksl*16 + 4j and k + 8.
    int bn = tid >> 2, sub = tid & 3;
    int bksl = sub >> 1, bj = sub & 1;
    int e0 = bn & 1;                 // store-order stagger (conflict-free phases)

    for (int t = blockIdx.x; t < TILES; t += GRID_GEMM) {
        int b = t / NTILES_B;
        int n0 = (t - b * NTILES_B) * NT;
        const float* xrow = g_x + ((size_t)b * NCOLS + n0 + bn) * CK + bksl * 16 + bj * 4;

        float4 p0 = *(const float4*)(xrow);
        float4 p1 = *(const float4*)(xrow + 8);

        float d[8][4];
        #pragma unroll
        for (int nt = 0; nt < 8; ++nt)
            #pragma unroll
            for (int r = 0; r < 4; ++r) d[nt][r] = 0.f;

        #pragma unroll 1
        for (int ch = 0; ch < 6; ++ch) {
            uint4* bb = Bq + (ch & 1) * BQBUF;
            // build 2 full quads, store with parity-staggered order
            {
                uint32_t h0a, l0a, h0b, l0b, h1a, l1a, h1b, l1b;
                split2(p0.x, p0.y, h0a, l0a);     // pair c4=2j, low half
                split2(p1.x, p1.y, h1a, l1a);     // pair c4=2j, +8 half
                split2(p0.z, p0.w, h0b, l0b);     // pair c4=2j+1, low half
                split2(p1.z, p1.w, h1b, l1b);     // pair c4=2j+1, +8 half
                uint4 q0 = make_uint4(h0a, l0a, h1a, l1a);
                uint4 q1 = make_uint4(h0b, l0b, h1b, l1b);
                int base = bn * BQROW + bksl * 4 + 2 * bj;
                bb[base + e0]       = e0 ? q1 : q0;
                bb[base + (1 - e0)] = e0 ? q0 : q1;
            }
            __syncthreads();
            if (ch < 5) {
                p0 = *(const float4*)(xrow + (ch + 1) * 32);
                p1 = *(const float4*)(xrow + (ch + 1) * 32 + 8);
            }
            // mma: 2 k16-steps per chunk
            #pragma unroll
            for (int ksl = 0; ksl < 2; ++ksl) {
                int ks = ch * 2 + ksl;
                uint4 q1a = Aq[(wm + lr) * AQROW + ks * 4 + lc];
                uint4 q2a = Aq[(wm + lr + 8) * AQROW + ks * 4 + lc];
                uint32_t ah[4] = {q1a.x, q2a.x, q1a.z, q2a.z};
                uint32_t al[4] = {q1a.y, q2a.y, q1a.w, q2a.w};
                #pragma unroll
                for (int nt = 0; nt < 8; ++nt) {
                    int nrow = wn + nt * 8 + lr;
                    uint4 qb = bb[nrow * BQROW + ksl * 4 + lc];
                    mma_bf16(d[nt], ah, qb.x, qb.z);
                    mma_bf16(d[nt], ah, qb.y, qb.w);
                    mma_bf16(d[nt], al, qb.x, qb.z);
                }
            }
        }

        // epilogue: direct STG.64 (+bias)
        size_t ro0 = ((size_t)b * CO + wm + lr) * NCOLS + n0 + wn + 2 * lc;
        size_t ro1 = ro0 + (size_t)8 * NCOLS;
        #pragma unroll
        for (int nt = 0; nt < 8; ++nt) {
            float2 v0 = { d[nt][0] + bz0, d[nt][1] + bz0 };
            float2 v1 = { d[nt][2] + bz1, d[nt][3] + bz1 };
            *(float2*)(out + ro0 + nt * 8) = v0;
            *(float2*)(out + ro1 + nt * 8) = v1;
        }
    }
}

// ---------------- host launcher ----------------
extern "C" void kernel_launch(void* const* d_in, const int* in_sizes, int n_in,
                              void* d_out, int out_size) {
    const float* feats     = (const float*)d_in[0];  // (2,64,1024,60) f32
    const float* intra_w   = (const float*)d_in[1];  // (60,3,8) f32
    const float* W         = (const float*)d_in[2];  // (128,192) f32
    const float* bias      = (const float*)d_in[3];  // (1,128,1) f32
    const int*   intra_idx = (const int*)d_in[4];    // (60,3,8) i32
    float* out = (float*)d_out;

    const int SMEM1 = (C_IN * (NA + 1) + 30 * CK) * 4 + NO * KS * ANN * 8;   // 50176
    const int SMEM2 = (CO * AQROW + 2 * BQBUF) * 16;                          // 155648

    static int configured = 0;
    if (!configured) {
        cudaFuncSetAttribute(k_gather,   cudaFuncAttributeMaxDynamicSharedMemorySize, SMEM1);
        cudaFuncSetAttribute(k_gemm_mma, cudaFuncAttributeMaxDynamicSharedMemorySize, SMEM2);
        configured = 1;
    }

    k_gather<<<dim3(NPTS, BSZ), 256, SMEM1>>>(feats, intra_w, intra_idx);
    k_gemm_mma<<<GRID_GEMM, 512, SMEM2>>>(W, bias, out);
}